// round 8
// baseline (speedup 1.0000x reference)
#include <cuda_runtime.h>
#include <cuda_bf16.h>
#include <cstdint>
#include <math.h>

// ===========================================================================
// LocalAttention: tcgen05 bf16x3-split GEMMs (256x256xBK32, SW64, depth-3)
//                 + f32x2-packed fp32 attention
//   B=8, DIM=512, H=W=128, WIN=8 -> 2048 windows x 64 tokens, HEADS=16, hd=32
//
// tcgen05.* / fma.rn.f32x2 are only legal on the 'a' feature target; the
// plain compute_103 pass gets scalar/FFMA fallbacks (never selected on GB300).
// ===========================================================================

#if defined(__CUDA_ARCH_FEAT_SM103_ALL) || defined(__CUDA_ARCH_FEAT_SM100_ALL) || defined(__CUDA_ARCH_FEAT_SM101_ALL)
#define HAS_TCGEN05 1
#else
#define HAS_TCGEN05 0
#endif

#define TOK      131072
#define NWIN     2048
#define NHEADS   16

// ---- scratch regions (byte offsets) ----
#define OFF_XAH  0ull
#define OFF_XAL  134217728ull
#define OFF_XBH  268435456ull
#define OFF_XBL  402653184ull
#define OFF_Q    536870912ull      // fp32 [TOK,512]
#define OFF_KV   805306368ull      // fp32 [TOK,1024]
#define OFF_AOH  OFF_XAH           // aliases XA (dead after Q GEMM)
#define OFF_AOL  OFF_XAL
#define OFF_OW   OFF_XBH           // fp32 [TOK,512], aliases XB (dead after KV GEMM)
#define OFF_WQH  1342177280ull
#define OFF_WQL  1342701568ull
#define OFF_WKVH 1343225856ull
#define OFF_WKVL 1344274432ull
#define OFF_WOH  1345323008ull
#define OFF_WOL  1345847296ull
// end = 1346371584

__device__ __align__(1024) unsigned char g_scratch[1346371584ull];

// ===========================================================================
// PTX helpers
// ===========================================================================
__device__ __forceinline__ uint32_t smem_u32(const void* p) {
    uint32_t a;
    asm("{ .reg .u64 t; cvta.to.shared.u64 t, %1; cvt.u32.u64 %0, t; }" : "=r"(a) : "l"(p));
    return a;
}
__device__ __forceinline__ uint32_t elect_one() {
    uint32_t pred;
    asm volatile("{\n\t.reg .pred p;\n\telect.sync _|p, 0xFFFFFFFF;\n\tselp.b32 %0, 1, 0, p;\n\t}" : "=r"(pred));
    return pred;
}
#define MBARRIER_INIT(addr, cnt) \
    asm volatile("mbarrier.init.shared.b64 [%0], %1;" :: "r"((uint32_t)(addr)), "r"((uint32_t)(cnt)) : "memory")
#define MBARRIER_INVAL(addr) \
    asm volatile("mbarrier.inval.shared.b64 [%0];" :: "r"((uint32_t)(addr)) : "memory")
#define MBARRIER_WAIT_PARITY(addr, par) do { \
    uint32_t _mb = (uint32_t)(addr); uint32_t _p = (uint32_t)(par); uint32_t _done; \
    asm volatile("{\n\t.reg .pred p;\n\t" \
        "mbarrier.try_wait.parity.acquire.cta.shared::cta.b64 p, [%1], %2;\n\t" \
        "selp.b32 %0, 1, 0, p;\n\t}" : "=r"(_done) : "r"(_mb), "r"(_p) : "memory"); \
    if (!_done) { \
        asm volatile("{\n\t.reg .pred P1;\n\t" \
            "WAIT_LOOP_%=:\n\t" \
            "mbarrier.try_wait.parity.acquire.cta.shared::cta.b64 P1, [%0], %1, 0x989680;\n\t" \
            "@P1 bra.uni WAIT_DONE_%=;\n\t" \
            "bra.uni WAIT_LOOP_%=;\n\t" \
            "WAIT_DONE_%=:\n\t}" :: "r"(_mb), "r"(_p) : "memory"); \
    } } while (0)
#define FENCE_ASYNC_SHARED()   asm volatile("fence.proxy.async.shared::cta;" ::: "memory")

#if HAS_TCGEN05
#define TCGEN05_ALLOC(sm, n) \
    asm volatile("tcgen05.alloc.cta_group::1.sync.aligned.shared::cta.b32 [%0], %1;" \
        :: "r"((uint32_t)(sm)), "r"((uint32_t)(n)) : "memory")
#define TCGEN05_DEALLOC(t, n) \
    asm volatile("tcgen05.dealloc.cta_group::1.sync.aligned.b32 %0, %1;" :: "r"(t), "r"((uint32_t)(n)))
#define TCGEN05_RELINQ() \
    asm volatile("tcgen05.relinquish_alloc_permit.cta_group::1.sync.aligned;")
#define TCGEN05_COMMIT(mb) \
    asm volatile("tcgen05.commit.cta_group::1.mbarrier::arrive::one.shared::cluster.b64 [%0];" \
        :: "r"((uint32_t)(mb)) : "memory")
#define TCGEN05_FENCE_AFTER()  asm volatile("tcgen05.fence::after_thread_sync;" ::: "memory")
#define TCGEN05_FENCE_BEFORE() asm volatile("tcgen05.fence::before_thread_sync;" ::: "memory")
#define TCGEN05_WAIT_LD()      asm volatile("tcgen05.wait::ld.sync.aligned;" ::: "memory")

#define TCGEN05_LD_X32(r, ta) \
    asm volatile("tcgen05.ld.sync.aligned.32x32b.x32.b32 " \
        "{%0, %1, %2, %3, %4, %5, %6, %7, " \
        " %8, %9, %10, %11, %12, %13, %14, %15, " \
        " %16, %17, %18, %19, %20, %21, %22, %23, " \
        " %24, %25, %26, %27, %28, %29, %30, %31}, [%32];" \
        : "=r"((r)[0]),  "=r"((r)[1]),  "=r"((r)[2]),  "=r"((r)[3]), \
          "=r"((r)[4]),  "=r"((r)[5]),  "=r"((r)[6]),  "=r"((r)[7]), \
          "=r"((r)[8]),  "=r"((r)[9]),  "=r"((r)[10]), "=r"((r)[11]), \
          "=r"((r)[12]), "=r"((r)[13]), "=r"((r)[14]), "=r"((r)[15]), \
          "=r"((r)[16]), "=r"((r)[17]), "=r"((r)[18]), "=r"((r)[19]), \
          "=r"((r)[20]), "=r"((r)[21]), "=r"((r)[22]), "=r"((r)[23]), \
          "=r"((r)[24]), "=r"((r)[25]), "=r"((r)[26]), "=r"((r)[27]), \
          "=r"((r)[28]), "=r"((r)[29]), "=r"((r)[30]), "=r"((r)[31]) \
        : "r"(ta))

__device__ __forceinline__ void mma_bf16_ss(uint32_t d, uint64_t ad, uint64_t bd,
                                            uint32_t idesc, uint32_t en) {
    asm volatile("{\n\t.reg .pred p;\n\tsetp.ne.u32 p, %5, 0;\n\t"
        "tcgen05.mma.cta_group::1.kind::f16 [%0], %1, %2, %3, {%4, %4, %4, %4}, p;\n\t}"
        :: "r"(d), "l"(ad), "l"(bd), "r"(idesc), "r"(0u), "r"(en) : "memory");
}
#endif // HAS_TCGEN05

// packed fp32 FMA: d = a*b + d (elementwise on 2 lanes). Exact fp32.
__device__ __forceinline__ void ffma2(unsigned long long& d,
                                      unsigned long long a, unsigned long long b) {
#if HAS_TCGEN05
    asm("fma.rn.f32x2 %0, %1, %2, %0;" : "+l"(d) : "l"(a), "l"(b));
#else
    float2 df = *(float2*)&d; float2 af = *(float2*)&a; float2 bf = *(float2*)&b;
    df.x = fmaf(af.x, bf.x, df.x);
    df.y = fmaf(af.y, bf.y, df.y);
    d = *(unsigned long long*)&df;
#endif
}
__device__ __forceinline__ float f2sum(unsigned long long v) {
    float2 f = *(float2*)&v;
    return f.x + f.y;
}

// SW64 smem descriptor: layout=4 (SW64), version=1 (Blackwell), SBO=32, LBO=1
static constexpr uint64_t SMEM_DESC_BASE_SW64 =
    (uint64_t(4) << 61) | (uint64_t(1) << 46) | (uint64_t(32) << 32) | (uint64_t(1) << 16);
#define MAKE_SMEM_DESC64(a) (SMEM_DESC_BASE_SW64 | ((uint64_t)((a) >> 4) & 0x3FFF))

__device__ __forceinline__ uint32_t sw64(uint32_t o) { return o ^ ((o >> 3) & 0x30); }

// kind::f16 SS MMA, cg1. D=fp32, A=B=bf16, M=128, N=128 (K=16 per step)
static constexpr uint32_t GEMM_IDESC =
    (1u << 4) | (1u << 7) | (1u << 10) | ((128u / 8) << 17) | ((128u / 16) << 24);

// ===========================================================================
// prep_w_all: all three weights fp32 -> bf16 hi/lo in ONE launch
//   Wq 262144 | Wkv 524288 | Wo 262144  (total 1048576 = 4096*256 exactly)
// ===========================================================================
__global__ __launch_bounds__(256) void prep_w_all(const float* __restrict__ Wq,
                                                  const float* __restrict__ Wkv,
                                                  const float* __restrict__ Wo)
{
    int i = blockIdx.x * 256 + threadIdx.x;
    const float* src; size_t hiOff, loOff; int j;
    if (i < 262144)      { src = Wq;  hiOff = OFF_WQH;  loOff = OFF_WQL;  j = i; }
    else if (i < 786432) { src = Wkv; hiOff = OFF_WKVH; loOff = OFF_WKVL; j = i - 262144; }
    else                 { src = Wo;  hiOff = OFF_WOH;  loOff = OFF_WOL;  j = i - 786432; }
    float x = src[j];
    __nv_bfloat16 h = __float2bfloat16(x);
    ((__nv_bfloat16*)(g_scratch + hiOff))[j] = h;
    ((__nv_bfloat16*)(g_scratch + loOff))[j] = __float2bfloat16(x - __bfloat162float(h));
}

// ===========================================================================
// gather_split: [B,C,H,W] fp32 -> token-major [TOK,512] bf16 hi/lo
// ===========================================================================
__global__ __launch_bounds__(256) void gather_split(const float* __restrict__ src,
                                                    size_t hiOff, size_t loOff)
{
    __shared__ float tile[32][129];
    __nv_bfloat16* dh = (__nv_bfloat16*)(g_scratch + hiOff);
    __nv_bfloat16* dl = (__nv_bfloat16*)(g_scratch + loOff);
    int bh = blockIdx.y;
    int b = bh >> 7, h = bh & 127;
    int c0 = blockIdx.x << 5;
    int tid = threadIdx.x;

    const float* srow = src + ((size_t)(b * 512 + c0) * 128 + h) * 128;
#pragma unroll
    for (int it = 0; it < 16; it++) {
        int idx = tid + it * 256;
        int cc = idx >> 7, w = idx & 127;
        tile[cc][w] = srow[(size_t)cc * 16384 + w];
    }
    __syncthreads();
    int r1 = h >> 3, i = h & 7;
#pragma unroll
    for (int it = 0; it < 16; it++) {
        int idx = tid + it * 256;
        int w = idx >> 5, cc = idx & 31;
        int r2 = w >> 3, j = w & 7;
        int t = ((b * 256 + r1 * 16 + r2) << 6) + i * 8 + j;
        float x = tile[cc][w];
        __nv_bfloat16 hv = __float2bfloat16(x);
        size_t o = (size_t)t * 512 + c0 + cc;
        dh[o] = hv;
        dl[o] = __float2bfloat16(x - __bfloat162float(hv));
    }
}

// ===========================================================================
// scatter: token-major fp32 [TOK,512] -> [B,C,H,W]
// ===========================================================================
__global__ __launch_bounds__(256) void scatter_win(float* __restrict__ dst)
{
    __shared__ float tile[32][129];
    const float* srcw = (const float*)(g_scratch + OFF_OW);
    int bh = blockIdx.y;
    int b = bh >> 7, h = bh & 127;
    int c0 = blockIdx.x << 5;
    int tid = threadIdx.x;
    int r1 = h >> 3, i = h & 7;

#pragma unroll
    for (int it = 0; it < 16; it++) {
        int idx = tid + it * 256;
        int w = idx >> 5, cc = idx & 31;
        int r2 = w >> 3, j = w & 7;
        int t = ((b * 256 + r1 * 16 + r2) << 6) + i * 8 + j;
        tile[cc][w] = srcw[(size_t)t * 512 + c0 + cc];
    }
    __syncthreads();
    float* drow = dst + ((size_t)(b * 512 + c0) * 128 + h) * 128;
#pragma unroll
    for (int it = 0; it < 16; it++) {
        int idx = tid + it * 256;
        int cc = idx >> 7, w = idx & 127;
        drow[(size_t)cc * 16384 + w] = tile[cc][w];
    }
}

// ===========================================================================
// gemm_bf16x3 (unchanged from R6 WIN): 256x256xBK32, SW64, depth-3 pipeline
// ===========================================================================
#define GEMM_SMEM 197632

__global__ __launch_bounds__(256) void gemm_bf16x3(
    size_t ahOff, size_t alOff, size_t bhOff, size_t blOff,
    const float* __restrict__ bias, size_t cOff, int No, float scale)
{
    extern __shared__ char smem[];
    const __nv_bfloat16* Ah = (const __nv_bfloat16*)(g_scratch + ahOff);
    const __nv_bfloat16* Al = (const __nv_bfloat16*)(g_scratch + alOff);
    const __nv_bfloat16* Bh = (const __nv_bfloat16*)(g_scratch + bhOff);
    const __nv_bfloat16* Bl = (const __nv_bfloat16*)(g_scratch + blOff);
    float* C = (float*)(g_scratch + cOff);

    int tid = threadIdx.x, wid = tid >> 5, lid = tid & 31;
    int n0 = blockIdx.x * 256, m0 = blockIdx.y * 256;

#if HAS_TCGEN05
    uint32_t sbase = smem_u32(smem);

    if (wid == 0) TCGEN05_ALLOC(sbase, 512);
    __syncthreads();
    uint32_t tmem;
    asm volatile("ld.shared.b32 %0, [%1];" : "=r"(tmem) : "r"(sbase));
    if (tid == 0) {
        MBARRIER_INIT(sbase + 16, 1);
        MBARRIER_INIT(sbase + 24, 1);
        MBARRIER_INIT(sbase + 32, 1);
    }
    __syncthreads();

    for (int kb = 0; kb < 16; kb++) {
        int buf = kb % 3;
        uint32_t bo = 1024u + (uint32_t)buf * 65536u;
        if (kb >= 3) {
            int j = kb / 3;
            MBARRIER_WAIT_PARITY(sbase + 16 + 8 * buf, (j - 1) & 1);
        }

        int k0 = kb * 32;
        const uint4* gAh = (const uint4*)(Ah + (size_t)m0 * 512 + k0);
        const uint4* gAl = (const uint4*)(Al + (size_t)m0 * 512 + k0);
        const uint4* gBh = (const uint4*)(Bh + (size_t)n0 * 512 + k0);
        const uint4* gBl = (const uint4*)(Bl + (size_t)n0 * 512 + k0);
#pragma unroll
        for (int t = 0; t < 4; t++) {
            int idx = tid + t * 256;
            int r = idx >> 2, c = idx & 3;
            uint32_t so = sw64((uint32_t)(r * 64 + c * 16));
            size_t ge = (size_t)r * 64 + c;
            *(uint4*)(smem + bo + so)          = gAh[ge];
            *(uint4*)(smem + bo + 16384 + so)  = gAl[ge];
            *(uint4*)(smem + bo + 32768 + so)  = gBh[ge];
            *(uint4*)(smem + bo + 49152 + so)  = gBl[ge];
        }
        __syncthreads();

        if (wid == 0) {
            FENCE_ASYNC_SHARED();
            if (elect_one()) {
                uint64_t dA[2] = { MAKE_SMEM_DESC64(sbase + bo),
                                   MAKE_SMEM_DESC64(sbase + bo + 16384) };
                uint64_t dB[2] = { MAKE_SMEM_DESC64(sbase + bo + 32768),
                                   MAKE_SMEM_DESC64(sbase + bo + 49152) };
                const int pa[3] = {0, 1, 0}, pb[3] = {0, 0, 1};
#pragma unroll
                for (int p = 0; p < 3; p++) {
                    uint64_t ad = dA[pa[p]], bd = dB[pb[p]];
#pragma unroll
                    for (int ks = 0; ks < 2; ks++) {
                        uint32_t en = !(kb == 0 && p == 0 && ks == 0);
#pragma unroll
                        for (int mh = 0; mh < 2; mh++) {
                            uint64_t adm = ad + mh * 512 + ks * 2;
                            mma_bf16_ss(tmem + mh * 256,       adm, bd + ks * 2,       GEMM_IDESC, en);
                            mma_bf16_ss(tmem + mh * 256 + 128, adm, bd + 512 + ks * 2, GEMM_IDESC, en);
                        }
                    }
                }
                TCGEN05_COMMIT(sbase + 16 + 8 * buf);
            }
        }
    }

    MBARRIER_WAIT_PARITY(sbase + 16, 1);
    TCGEN05_FENCE_AFTER();

    float* stage = (float*)(smem + 1024);
#pragma unroll 1
    for (int mh = 0; mh < 2; mh++) {
        {
            int sp = wid & 3;
            int cbase = (wid >> 2) * 128;
#pragma unroll
            for (int cc = 0; cc < 128; cc += 32) {
                uint32_t r[32];
                TCGEN05_LD_X32(r, tmem + mh * 256 + cbase + cc);
                TCGEN05_WAIT_LD();
                float* row = stage + (size_t)(sp * 32 + lid) * 260 + cbase + cc;
#pragma unroll
                for (int i = 0; i < 8; i++) {
                    float4 v = make_float4(__uint_as_float(r[4 * i]), __uint_as_float(r[4 * i + 1]),
                                           __uint_as_float(r[4 * i + 2]), __uint_as_float(r[4 * i + 3]));
                    *(float4*)(row + 4 * i) = v;
                }
            }
        }
        TCGEN05_FENCE_BEFORE();
        __syncthreads();

#pragma unroll
        for (int t = 0; t < 32; t++) {
            int j = tid + t * 256;
            int r = j >> 6, c4 = j & 63;
            float4 v = *(float4*)(stage + (size_t)r * 260 + c4 * 4);
            float4 b = *(const float4*)(bias + n0 + c4 * 4);
            float4 o;
            o.x = (v.x + b.x) * scale;
            o.y = (v.y + b.y) * scale;
            o.z = (v.z + b.z) * scale;
            o.w = (v.w + b.w) * scale;
            *(float4*)(C + (size_t)(m0 + mh * 128 + r) * No + n0 + c4 * 4) = o;
        }
        __syncthreads();
    }

    if (tid == 0) {
        MBARRIER_INVAL(sbase + 16);
        MBARRIER_INVAL(sbase + 24);
        MBARRIER_INVAL(sbase + 32);
    }
    __syncthreads();
    if (wid == 0) { TCGEN05_RELINQ(); TCGEN05_DEALLOC(tmem, 512); }

#else  // ---- FFMA fallback for the plain compute_103 pass ----
    float* As = (float*)smem;
    float* Bs = (float*)(smem + 16 * 128 * 4);
    int tx = tid & 15, ty = tid >> 4;

    for (int msub = 0; msub < 2; msub++) {
        int m0c = m0 + msub * 128;
        for (int nsub = 0; nsub < 4; nsub++) {
            int nc0 = n0 + nsub * 64;
            float acc[8][4];
#pragma unroll
            for (int u = 0; u < 8; u++)
#pragma unroll
                for (int v = 0; v < 4; v++) acc[u][v] = 0.f;

            for (int k0 = 0; k0 < 512; k0 += 16) {
#pragma unroll
                for (int t = 0; t < 8; t++) {
                    int e = tid + t * 256;
                    int r = e & 127, kk = e >> 7;
                    size_t g = (size_t)(m0c + r) * 512 + k0 + kk;
                    As[kk * 128 + r] = __bfloat162float(Ah[g]) + __bfloat162float(Al[g]);
                }
#pragma unroll
                for (int t = 0; t < 4; t++) {
                    int e = tid + t * 256;
                    int r = e & 63, kk = e >> 6;
                    size_t g = (size_t)(nc0 + r) * 512 + k0 + kk;
                    Bs[kk * 64 + r] = __bfloat162float(Bh[g]) + __bfloat162float(Bl[g]);
                }
                __syncthreads();
#pragma unroll
                for (int kk = 0; kk < 16; kk++) {
                    float a[8], b[4];
#pragma unroll
                    for (int u = 0; u < 8; u++) a[u] = As[kk * 128 + ty * 8 + u];
#pragma unroll
                    for (int v = 0; v < 4; v++) b[v] = Bs[kk * 64 + tx * 4 + v];
#pragma unroll
                    for (int u = 0; u < 8; u++)
#pragma unroll
                        for (int v = 0; v < 4; v++) acc[u][v] += a[u] * b[v];
                }
                __syncthreads();
            }

#pragma unroll
            for (int u = 0; u < 8; u++)
#pragma unroll
                for (int v = 0; v < 4; v++)
                    C[(size_t)(m0c + ty * 8 + u) * No + nc0 + tx * 4 + v] =
                        (acc[u][v] + bias[nc0 + tx * 4 + v]) * scale;
            __syncthreads();
        }
    }
#endif
}

// ===========================================================================
// attention: one block per (window, head); f32x2-packed contraction loops.
//   qs/ks row stride 34 (even -> 8B aligned d-pairs); V stored transposed
//   (vst[32][66], nk-contiguous) so PV packs along nk.
// ===========================================================================
__global__ __launch_bounds__(256) void attn_kernel(const float* __restrict__ rpb,
                                                   const int* __restrict__ relidx)
{
    __shared__ float qs[64][34];
    __shared__ float ks[64][34];
    __shared__ float vst[32][66];
    __shared__ float ps[64][68];

    const float* Q  = (const float*)(g_scratch + OFF_Q);
    const float* KV = (const float*)(g_scratch + OFF_KV);
    __nv_bfloat16* AOh = (__nv_bfloat16*)(g_scratch + OFF_AOH);
    __nv_bfloat16* AOl = (__nv_bfloat16*)(g_scratch + OFF_AOL);

    int m = blockIdx.x;
    int h = blockIdx.y;
    int tid = threadIdx.x;
    size_t tb = (size_t)m * 64;

#pragma unroll
    for (int it = 0; it < 8; it++) {
        int idx = tid + it * 256;
        int n = idx >> 5, d = idx & 31;
        qs[n][d]  = Q[(tb + n) * 512 + h * 32 + d];
        ks[n][d]  = KV[(tb + n) * 1024 + h * 32 + d];
        vst[d][n] = KV[(tb + n) * 1024 + 512 + h * 32 + d];
    }
    __syncthreads();

    // ---- S = q k^T (64x64), 4x4 per thread, packed along d ----
    {
        int tx = tid & 15, ty = tid >> 4;
        unsigned long long acc2[4][4];
#pragma unroll
        for (int u = 0; u < 4; u++)
#pragma unroll
            for (int v = 0; v < 4; v++) acc2[u][v] = 0ull;
#pragma unroll
        for (int dp = 0; dp < 16; dp++) {
            unsigned long long a2[4], b2[4];
#pragma unroll
            for (int u = 0; u < 4; u++)
                a2[u] = *(const unsigned long long*)&qs[ty * 4 + u][2 * dp];
#pragma unroll
            for (int v = 0; v < 4; v++)
                b2[v] = *(const unsigned long long*)&ks[tx * 4 + v][2 * dp];
#pragma unroll
            for (int u = 0; u < 4; u++)
#pragma unroll
                for (int v = 0; v < 4; v++) ffma2(acc2[u][v], a2[u], b2[v]);
        }
#pragma unroll
        for (int u = 0; u < 4; u++)
#pragma unroll
            for (int v = 0; v < 4; v++) {
                int mq = ty * 4 + u, nk = tx * 4 + v;
                int ri = relidx[mq * 64 + nk];
                ps[mq][nk] = f2sum(acc2[u][v]) + rpb[ri * NHEADS + h];
            }
    }
    __syncthreads();

    // ---- softmax per row (4 lanes per row) ----
    {
        int g = tid & 3, row = tid >> 2;
        float mx = -1e30f;
        for (int c = g; c < 64; c += 4) mx = fmaxf(mx, ps[row][c]);
        mx = fmaxf(mx, __shfl_xor_sync(0xffffffffu, mx, 1));
        mx = fmaxf(mx, __shfl_xor_sync(0xffffffffu, mx, 2));
        float sum = 0.f;
        for (int c = g; c < 64; c += 4) {
            float e = __expf(ps[row][c] - mx);
            ps[row][c] = e;
            sum += e;
        }
        sum += __shfl_xor_sync(0xffffffffu, sum, 1);
        sum += __shfl_xor_sync(0xffffffffu, sum, 2);
        float inv = 1.f / sum;
        for (int c = g; c < 64; c += 4) ps[row][c] *= inv;
    }
    __syncthreads();

    // ---- out = P v (64x32), 2x4 per thread, packed along nk ----
    {
        int tx = tid & 7, ty = tid >> 3;
        unsigned long long acc2[2][4];
#pragma unroll
        for (int u = 0; u < 2; u++)
#pragma unroll
            for (int v = 0; v < 4; v++) acc2[u][v] = 0ull;
#pragma unroll
        for (int np = 0; np < 32; np++) {
            unsigned long long p2_0 = *(const unsigned long long*)&ps[ty * 2 + 0][2 * np];
            unsigned long long p2_1 = *(const unsigned long long*)&ps[ty * 2 + 1][2 * np];
#pragma unroll
            for (int v = 0; v < 4; v++) {
                unsigned long long v2 = *(const unsigned long long*)&vst[tx * 4 + v][2 * np];
                ffma2(acc2[0][v], p2_0, v2);
                ffma2(acc2[1][v], p2_1, v2);
            }
        }
#pragma unroll
        for (int u = 0; u < 2; u++) {
            size_t o = (tb + ty * 2 + u) * 512 + h * 32 + tx * 4;
            unsigned short hh[4], ll[4];
#pragma unroll
            for (int v = 0; v < 4; v++) {
                float x = f2sum(acc2[u][v]);
                __nv_bfloat16 hv = __float2bfloat16(x);
                __nv_bfloat16 lv = __float2bfloat16(x - __bfloat162float(hv));
                hh[v] = *(unsigned short*)&hv;
                ll[v] = *(unsigned short*)&lv;
            }
            uint2 ph = make_uint2((uint32_t)hh[0] | ((uint32_t)hh[1] << 16),
                                  (uint32_t)hh[2] | ((uint32_t)hh[3] << 16));
            uint2 pl = make_uint2((uint32_t)ll[0] | ((uint32_t)ll[1] << 16),
                                  (uint32_t)ll[2] | ((uint32_t)ll[3] << 16));
            *(uint2*)(AOh + o) = ph;
            *(uint2*)(AOl + o) = pl;
        }
    }
}

// ===========================================================================
extern "C" void kernel_launch(void* const* d_in, const int* in_sizes, int n_in,
                              void* d_out, int out_size)
{
    const float* xa     = (const float*)d_in[0];
    const float* xb     = (const float*)d_in[1];
    const float* Wq     = (const float*)d_in[2];
    const float* bq     = (const float*)d_in[3];
    const float* Wkv    = (const float*)d_in[4];
    const float* bkv    = (const float*)d_in[5];
    const float* Wo     = (const float*)d_in[6];
    const float* bo     = (const float*)d_in[7];
    const float* rpb    = (const float*)d_in[8];
    const int*   relidx = (const int*)d_in[9];
    float* out = (float*)d_out;

    const float scale = 0.17677669529663687f; // 32^-0.5

    // idempotent, non-enqueuing, capture-safe
    cudaFuncSetAttribute(gemm_bf16x3, cudaFuncAttributeMaxDynamicSharedMemorySize, GEMM_SMEM);

    dim3 gwin(16, 1024);
    // Launch order: attn is the 6th launch (ncu -s 5 -c 1 captures it).
    prep_w_all<<<4096, 256>>>(Wq, Wkv, Wo);                               // 1
    gather_split<<<gwin, 256>>>(xa, OFF_XAH, OFF_XAL);                    // 2
    gather_split<<<gwin, 256>>>(xb, OFF_XBH, OFF_XBL);                    // 3

    gemm_bf16x3<<<dim3(2, 512), 256, GEMM_SMEM>>>(OFF_XAH, OFF_XAL,       // 4
                                                  OFF_WQH, OFF_WQL,
                                                  bq, OFF_Q, 512, scale);
    gemm_bf16x3<<<dim3(4, 512), 256, GEMM_SMEM>>>(OFF_XBH, OFF_XBL,       // 5
                                                  OFF_WKVH, OFF_WKVL,
                                                  bkv, OFF_KV, 1024, 1.0f);

    attn_kernel<<<dim3(NWIN, NHEADS), 256>>>(rpb, relidx);                // 6 <- profiled

    gemm_bf16x3<<<dim3(2, 512), 256, GEMM_SMEM>>>(OFF_AOH, OFF_AOL,       // 7
                                                  OFF_WOH, OFF_WOL,
                                                  bo, OFF_OW, 512, 1.0f);

    scatter_win<<<gwin, 256>>>(out);                                      // 8
}

// round 10
// speedup vs baseline: 1.1397x; 1.1397x over previous
#include <cuda_runtime.h>
#include <cuda_bf16.h>
#include <cstdint>
#include <math.h>

// ===========================================================================
// LocalAttention: warp-specialized tcgen05 bf16x3-split GEMMs
//   (256x256xBK32, SW64, depth-3, loader-warps + MMA-issuer warp)
//   + scalar fp32 attention (R6 known-good)
// ===========================================================================

#if defined(__CUDA_ARCH_FEAT_SM103_ALL) || defined(__CUDA_ARCH_FEAT_SM100_ALL) || defined(__CUDA_ARCH_FEAT_SM101_ALL)
#define HAS_TCGEN05 1
#else
#define HAS_TCGEN05 0
#endif

#define TOK      131072
#define NWIN     2048
#define NHEADS   16

// ---- scratch regions (byte offsets) ----
#define OFF_XAH  0ull
#define OFF_XAL  134217728ull
#define OFF_XBH  268435456ull
#define OFF_XBL  402653184ull
#define OFF_Q    536870912ull      // fp32 [TOK,512]
#define OFF_KV   805306368ull      // fp32 [TOK,1024]
#define OFF_AOH  OFF_XAH           // aliases XA (dead after Q GEMM)
#define OFF_AOL  OFF_XAL
#define OFF_OW   OFF_XBH           // fp32 [TOK,512], aliases XB (dead after KV GEMM)
#define OFF_WQH  1342177280ull
#define OFF_WQL  1342701568ull
#define OFF_WKVH 1343225856ull
#define OFF_WKVL 1344274432ull
#define OFF_WOH  1345323008ull
#define OFF_WOL  1345847296ull

__device__ __align__(1024) unsigned char g_scratch[1346371584ull];

// ===========================================================================
// PTX helpers
// ===========================================================================
__device__ __forceinline__ uint32_t smem_u32(const void* p) {
    uint32_t a;
    asm("{ .reg .u64 t; cvta.to.shared.u64 t, %1; cvt.u32.u64 %0, t; }" : "=r"(a) : "l"(p));
    return a;
}
__device__ __forceinline__ uint32_t elect_one() {
    uint32_t pred;
    asm volatile("{\n\t.reg .pred p;\n\telect.sync _|p, 0xFFFFFFFF;\n\tselp.b32 %0, 1, 0, p;\n\t}" : "=r"(pred));
    return pred;
}
#define MBARRIER_INIT(addr, cnt) \
    asm volatile("mbarrier.init.shared.b64 [%0], %1;" :: "r"((uint32_t)(addr)), "r"((uint32_t)(cnt)) : "memory")
#define MBARRIER_INVAL(addr) \
    asm volatile("mbarrier.inval.shared.b64 [%0];" :: "r"((uint32_t)(addr)) : "memory")
#define MBARRIER_ARRIVE(addr) \
    asm volatile("mbarrier.arrive.shared.b64 _, [%0];" :: "r"((uint32_t)(addr)) : "memory")
#define MBARRIER_WAIT_PARITY(addr, par) do { \
    uint32_t _mb = (uint32_t)(addr); uint32_t _p = (uint32_t)(par); uint32_t _done; \
    asm volatile("{\n\t.reg .pred p;\n\t" \
        "mbarrier.try_wait.parity.acquire.cta.shared::cta.b64 p, [%1], %2;\n\t" \
        "selp.b32 %0, 1, 0, p;\n\t}" : "=r"(_done) : "r"(_mb), "r"(_p) : "memory"); \
    if (!_done) { \
        asm volatile("{\n\t.reg .pred P1;\n\t" \
            "WAIT_LOOP_%=:\n\t" \
            "mbarrier.try_wait.parity.acquire.cta.shared::cta.b64 P1, [%0], %1, 0x989680;\n\t" \
            "@P1 bra.uni WAIT_DONE_%=;\n\t" \
            "bra.uni WAIT_LOOP_%=;\n\t" \
            "WAIT_DONE_%=:\n\t}" :: "r"(_mb), "r"(_p) : "memory"); \
    } } while (0)
#define FENCE_ASYNC_SHARED()   asm volatile("fence.proxy.async.shared::cta;" ::: "memory")

#if HAS_TCGEN05
#define TCGEN05_ALLOC(sm, n) \
    asm volatile("tcgen05.alloc.cta_group::1.sync.aligned.shared::cta.b32 [%0], %1;" \
        :: "r"((uint32_t)(sm)), "r"((uint32_t)(n)) : "memory")
#define TCGEN05_DEALLOC(t, n) \
    asm volatile("tcgen05.dealloc.cta_group::1.sync.aligned.b32 %0, %1;" :: "r"(t), "r"((uint32_t)(n)))
#define TCGEN05_RELINQ() \
    asm volatile("tcgen05.relinquish_alloc_permit.cta_group::1.sync.aligned;")
#define TCGEN05_COMMIT(mb) \
    asm volatile("tcgen05.commit.cta_group::1.mbarrier::arrive::one.shared::cluster.b64 [%0];" \
        :: "r"((uint32_t)(mb)) : "memory")
#define TCGEN05_FENCE_AFTER()  asm volatile("tcgen05.fence::after_thread_sync;" ::: "memory")
#define TCGEN05_FENCE_BEFORE() asm volatile("tcgen05.fence::before_thread_sync;" ::: "memory")
#define TCGEN05_WAIT_LD()      asm volatile("tcgen05.wait::ld.sync.aligned;" ::: "memory")

#define TCGEN05_LD_X32(r, ta) \
    asm volatile("tcgen05.ld.sync.aligned.32x32b.x32.b32 " \
        "{%0, %1, %2, %3, %4, %5, %6, %7, " \
        " %8, %9, %10, %11, %12, %13, %14, %15, " \
        " %16, %17, %18, %19, %20, %21, %22, %23, " \
        " %24, %25, %26, %27, %28, %29, %30, %31}, [%32];" \
        : "=r"((r)[0]),  "=r"((r)[1]),  "=r"((r)[2]),  "=r"((r)[3]), \
          "=r"((r)[4]),  "=r"((r)[5]),  "=r"((r)[6]),  "=r"((r)[7]), \
          "=r"((r)[8]),  "=r"((r)[9]),  "=r"((r)[10]), "=r"((r)[11]), \
          "=r"((r)[12]), "=r"((r)[13]), "=r"((r)[14]), "=r"((r)[15]), \
          "=r"((r)[16]), "=r"((r)[17]), "=r"((r)[18]), "=r"((r)[19]), \
          "=r"((r)[20]), "=r"((r)[21]), "=r"((r)[22]), "=r"((r)[23]), \
          "=r"((r)[24]), "=r"((r)[25]), "=r"((r)[26]), "=r"((r)[27]), \
          "=r"((r)[28]), "=r"((r)[29]), "=r"((r)[30]), "=r"((r)[31]) \
        : "r"(ta))

__device__ __forceinline__ void mma_bf16_ss(uint32_t d, uint64_t ad, uint64_t bd,
                                            uint32_t idesc, uint32_t en) {
    asm volatile("{\n\t.reg .pred p;\n\tsetp.ne.u32 p, %5, 0;\n\t"
        "tcgen05.mma.cta_group::1.kind::f16 [%0], %1, %2, %3, {%4, %4, %4, %4}, p;\n\t}"
        :: "r"(d), "l"(ad), "l"(bd), "r"(idesc), "r"(0u), "r"(en) : "memory");
}
#endif // HAS_TCGEN05

// SW64 smem descriptor: layout=4 (SW64), version=1 (Blackwell), SBO=32, LBO=1
static constexpr uint64_t SMEM_DESC_BASE_SW64 =
    (uint64_t(4) << 61) | (uint64_t(1) << 46) | (uint64_t(32) << 32) | (uint64_t(1) << 16);
#define MAKE_SMEM_DESC64(a) (SMEM_DESC_BASE_SW64 | ((uint64_t)((a) >> 4) & 0x3FFF))

__device__ __forceinline__ uint32_t sw64(uint32_t o) { return o ^ ((o >> 3) & 0x30); }

// kind::f16 SS MMA, cg1. D=fp32, A=B=bf16, M=128, N=128 (K=16 per step)
static constexpr uint32_t GEMM_IDESC =
    (1u << 4) | (1u << 7) | (1u << 10) | ((128u / 8) << 17) | ((128u / 16) << 24);

// ===========================================================================
// prep_w_all: all three weights fp32 -> bf16 hi/lo in ONE launch
// ===========================================================================
__global__ __launch_bounds__(256) void prep_w_all(const float* __restrict__ Wq,
                                                  const float* __restrict__ Wkv,
                                                  const float* __restrict__ Wo)
{
    int i = blockIdx.x * 256 + threadIdx.x;
    const float* src; size_t hiOff, loOff; int j;
    if (i < 262144)      { src = Wq;  hiOff = OFF_WQH;  loOff = OFF_WQL;  j = i; }
    else if (i < 786432) { src = Wkv; hiOff = OFF_WKVH; loOff = OFF_WKVL; j = i - 262144; }
    else                 { src = Wo;  hiOff = OFF_WOH;  loOff = OFF_WOL;  j = i - 786432; }
    float x = src[j];
    __nv_bfloat16 h = __float2bfloat16(x);
    ((__nv_bfloat16*)(g_scratch + hiOff))[j] = h;
    ((__nv_bfloat16*)(g_scratch + loOff))[j] = __float2bfloat16(x - __bfloat162float(h));
}

// ===========================================================================
// gather_split: [B,C,H,W] fp32 -> token-major [TOK,512] bf16 hi/lo
// ===========================================================================
__global__ __launch_bounds__(256) void gather_split(const float* __restrict__ src,
                                                    size_t hiOff, size_t loOff)
{
    __shared__ float tile[32][129];
    __nv_bfloat16* dh = (__nv_bfloat16*)(g_scratch + hiOff);
    __nv_bfloat16* dl = (__nv_bfloat16*)(g_scratch + loOff);
    int bh = blockIdx.y;
    int b = bh >> 7, h = bh & 127;
    int c0 = blockIdx.x << 5;
    int tid = threadIdx.x;

    const float* srow = src + ((size_t)(b * 512 + c0) * 128 + h) * 128;
#pragma unroll
    for (int it = 0; it < 16; it++) {
        int idx = tid + it * 256;
        int cc = idx >> 7, w = idx & 127;
        tile[cc][w] = srow[(size_t)cc * 16384 + w];
    }
    __syncthreads();
    int r1 = h >> 3, i = h & 7;
#pragma unroll
    for (int it = 0; it < 16; it++) {
        int idx = tid + it * 256;
        int w = idx >> 5, cc = idx & 31;
        int r2 = w >> 3, j = w & 7;
        int t = ((b * 256 + r1 * 16 + r2) << 6) + i * 8 + j;
        float x = tile[cc][w];
        __nv_bfloat16 hv = __float2bfloat16(x);
        size_t o = (size_t)t * 512 + c0 + cc;
        dh[o] = hv;
        dl[o] = __float2bfloat16(x - __bfloat162float(hv));
    }
}

// ===========================================================================
// scatter: token-major fp32 [TOK,512] -> [B,C,H,W]
// ===========================================================================
__global__ __launch_bounds__(256) void scatter_win(float* __restrict__ dst)
{
    __shared__ float tile[32][129];
    const float* srcw = (const float*)(g_scratch + OFF_OW);
    int bh = blockIdx.y;
    int b = bh >> 7, h = bh & 127;
    int c0 = blockIdx.x << 5;
    int tid = threadIdx.x;
    int r1 = h >> 3, i = h & 7;

#pragma unroll
    for (int it = 0; it < 16; it++) {
        int idx = tid + it * 256;
        int w = idx >> 5, cc = idx & 31;
        int r2 = w >> 3, j = w & 7;
        int t = ((b * 256 + r1 * 16 + r2) << 6) + i * 8 + j;
        tile[cc][w] = srcw[(size_t)t * 512 + c0 + cc];
    }
    __syncthreads();
    float* drow = dst + ((size_t)(b * 512 + c0) * 128 + h) * 128;
#pragma unroll
    for (int it = 0; it < 16; it++) {
        int idx = tid + it * 256;
        int cc = idx >> 7, w = idx & 127;
        drow[(size_t)cc * 16384 + w] = tile[cc][w];
    }
}

// ===========================================================================
// gemm_bf16x3: warp-specialized. 288 threads: warps 0-7 load, warp 8 issues.
//   Tile 256x256, BK=32 (SW64), depth-3. bf16x3 split, fp32 TMEM accumulate.
// smem: [0] tmem ptr | full[3] @16,24,32 (count 256) | free[3] @40,48,56 (count 1)
//       buffers @1024 + s*65536 : Ah 16K | Al 16K | Bh 16K | Bl 16K
// Epilogue: direct LDTM -> STG.128 (each lane owns contiguous 128B of C row).
// ===========================================================================
#define GEMM_SMEM  197632
#define GEMM_THREADS 288

__global__ __launch_bounds__(GEMM_THREADS) void gemm_bf16x3(
    size_t ahOff, size_t alOff, size_t bhOff, size_t blOff,
    const float* __restrict__ bias, size_t cOff, int No, float scale)
{
    extern __shared__ char smem[];
    const __nv_bfloat16* Ah = (const __nv_bfloat16*)(g_scratch + ahOff);
    const __nv_bfloat16* Al = (const __nv_bfloat16*)(g_scratch + alOff);
    const __nv_bfloat16* Bh = (const __nv_bfloat16*)(g_scratch + bhOff);
    const __nv_bfloat16* Bl = (const __nv_bfloat16*)(g_scratch + blOff);
    float* C = (float*)(g_scratch + cOff);

    int tid = threadIdx.x, wid = tid >> 5, lid = tid & 31;
    int n0 = blockIdx.x * 256, m0 = blockIdx.y * 256;

#if HAS_TCGEN05
    uint32_t sbase = smem_u32(smem);

    if (wid == 0) TCGEN05_ALLOC(sbase, 512);
    __syncthreads();
    uint32_t tmem;
    asm volatile("ld.shared.b32 %0, [%1];" : "=r"(tmem) : "r"(sbase));
    if (tid == 0) {
#pragma unroll
        for (int s = 0; s < 3; s++) {
            MBARRIER_INIT(sbase + 16 + 8 * s, 256);  // full[s]
            MBARRIER_INIT(sbase + 40 + 8 * s, 1);    // free[s]
        }
    }
    __syncthreads();

    if (tid < 256) {
        // -------- loader warps 0-7 --------
        for (int kb = 0; kb < 16; kb++) {
            int buf = kb % 3;
            uint32_t bo = 1024u + (uint32_t)buf * 65536u;
            if (kb >= 3) {
                int t = kb / 3;                       // wait free[buf] completion #t
                MBARRIER_WAIT_PARITY(sbase + 40 + 8 * buf, (t - 1) & 1);
            }
            int k0 = kb * 32;
            const uint4* gAh = (const uint4*)(Ah + (size_t)m0 * 512 + k0);
            const uint4* gAl = (const uint4*)(Al + (size_t)m0 * 512 + k0);
            const uint4* gBh = (const uint4*)(Bh + (size_t)n0 * 512 + k0);
            const uint4* gBl = (const uint4*)(Bl + (size_t)n0 * 512 + k0);
#pragma unroll
            for (int t = 0; t < 4; t++) {
                int idx = tid + t * 256;
                int r = idx >> 2, c = idx & 3;
                uint32_t so = sw64((uint32_t)(r * 64 + c * 16));
                size_t ge = (size_t)r * 64 + c;
                *(uint4*)(smem + bo + so)          = gAh[ge];
                *(uint4*)(smem + bo + 16384 + so)  = gAl[ge];
                *(uint4*)(smem + bo + 32768 + so)  = gBh[ge];
                *(uint4*)(smem + bo + 49152 + so)  = gBl[ge];
            }
            FENCE_ASYNC_SHARED();
            MBARRIER_ARRIVE(sbase + 16 + 8 * buf);
        }
    } else {
        // -------- MMA issuer warp 8 --------
        for (int kb = 0; kb < 16; kb++) {
            int buf = kb % 3;
            uint32_t bo = 1024u + (uint32_t)buf * 65536u;
            int t = kb / 3;                           // wait full[buf] completion #(t+1)
            MBARRIER_WAIT_PARITY(sbase + 16 + 8 * buf, t & 1);
            if (elect_one()) {
                uint64_t dA[2] = { MAKE_SMEM_DESC64(sbase + bo),
                                   MAKE_SMEM_DESC64(sbase + bo + 16384) };
                uint64_t dB[2] = { MAKE_SMEM_DESC64(sbase + bo + 32768),
                                   MAKE_SMEM_DESC64(sbase + bo + 49152) };
                const int pa[3] = {0, 1, 0}, pb[3] = {0, 0, 1};
#pragma unroll
                for (int p = 0; p < 3; p++) {
                    uint64_t ad = dA[pa[p]], bd = dB[pb[p]];
#pragma unroll
                    for (int ks = 0; ks < 2; ks++) {
                        uint32_t en = !(kb == 0 && p == 0 && ks == 0);
#pragma unroll
                        for (int mh = 0; mh < 2; mh++) {
                            uint64_t adm = ad + mh * 512 + ks * 2;
                            mma_bf16_ss(tmem + mh * 256,       adm, bd + ks * 2,       GEMM_IDESC, en);
                            mma_bf16_ss(tmem + mh * 256 + 128, adm, bd + 512 + ks * 2, GEMM_IDESC, en);
                        }
                    }
                }
                TCGEN05_COMMIT(sbase + 40 + 8 * buf);
            }
        }
    }

    // free[0] completions land at kb=0,3,6,9,12,15 -> 6 total; loaders consumed
    // up to #5 in-loop (so >=5 done when any thread reaches here). Wait #6 ->
    // parity 1 blocks at parity-1 state (after #5) until #6 flips it.
    MBARRIER_WAIT_PARITY(sbase + 40, 1);
    TCGEN05_FENCE_AFTER();

    // ---- epilogue: direct TMEM -> registers -> STG.128 (warps 0-7) ----
    if (wid < 8) {
        int sp = wid & 3;             // subpartition rows sp*32 + lid
        int cbase = (wid >> 2) * 128; // warps 0-3: cols 0-127, 4-7: 128-255
#pragma unroll 1
        for (int mh = 0; mh < 2; mh++) {
            int row = m0 + mh * 128 + sp * 32 + lid;
            float* Crow = C + (size_t)row * No + n0 + cbase;
#pragma unroll
            for (int cc = 0; cc < 128; cc += 32) {
                uint32_t r[32];
                TCGEN05_LD_X32(r, tmem + mh * 256 + cbase + cc);
                TCGEN05_WAIT_LD();
#pragma unroll
                for (int i = 0; i < 8; i++) {
                    float4 b = *(const float4*)(bias + n0 + cbase + cc + 4 * i);
                    float4 o;
                    o.x = (__uint_as_float(r[4 * i + 0]) + b.x) * scale;
                    o.y = (__uint_as_float(r[4 * i + 1]) + b.y) * scale;
                    o.z = (__uint_as_float(r[4 * i + 2]) + b.z) * scale;
                    o.w = (__uint_as_float(r[4 * i + 3]) + b.w) * scale;
                    *(float4*)(Crow + cc + 4 * i) = o;
                }
            }
        }
        TCGEN05_FENCE_BEFORE();
    }

    __syncthreads();
    if (tid == 0) {
#pragma unroll
        for (int s = 0; s < 3; s++) {
            MBARRIER_INVAL(sbase + 16 + 8 * s);
            MBARRIER_INVAL(sbase + 40 + 8 * s);
        }
    }
    __syncthreads();
    if (wid == 0) { TCGEN05_RELINQ(); TCGEN05_DEALLOC(tmem, 512); }

#else  // ---- FFMA fallback for the plain compute_103 pass ----
    float* As = (float*)smem;
    float* Bs = (float*)(smem + 16 * 128 * 4);
    int tx = tid & 15, ty = tid >> 4;

    for (int msub = 0; msub < 2; msub++) {
        int m0c = m0 + msub * 128;
        for (int nsub = 0; nsub < 4; nsub++) {
            int nc0 = n0 + nsub * 64;
            float acc[8][4];
#pragma unroll
            for (int u = 0; u < 8; u++)
#pragma unroll
                for (int v = 0; v < 4; v++) acc[u][v] = 0.f;

            for (int k0 = 0; k0 < 512; k0 += 16) {
                if (tid < 256) {
#pragma unroll
                    for (int t = 0; t < 8; t++) {
                        int e = tid + t * 256;
                        int r = e & 127, kk = e >> 7;
                        size_t g = (size_t)(m0c + r) * 512 + k0 + kk;
                        As[kk * 128 + r] = __bfloat162float(Ah[g]) + __bfloat162float(Al[g]);
                    }
#pragma unroll
                    for (int t = 0; t < 4; t++) {
                        int e = tid + t * 256;
                        int r = e & 63, kk = e >> 6;
                        size_t g = (size_t)(nc0 + r) * 512 + k0 + kk;
                        Bs[kk * 64 + r] = __bfloat162float(Bh[g]) + __bfloat162float(Bl[g]);
                    }
                }
                __syncthreads();
                if (tid < 256) {
#pragma unroll
                    for (int kk = 0; kk < 16; kk++) {
                        float a[8], b[4];
#pragma unroll
                        for (int u = 0; u < 8; u++) a[u] = As[kk * 128 + ty * 8 + u];
#pragma unroll
                        for (int v = 0; v < 4; v++) b[v] = Bs[kk * 64 + tx * 4 + v];
#pragma unroll
                        for (int u = 0; u < 8; u++)
#pragma unroll
                            for (int v = 0; v < 4; v++) acc[u][v] += a[u] * b[v];
                    }
                }
                __syncthreads();
            }

            if (tid < 256) {
#pragma unroll
                for (int u = 0; u < 8; u++)
#pragma unroll
                    for (int v = 0; v < 4; v++)
                        C[(size_t)(m0c + ty * 8 + u) * No + nc0 + tx * 4 + v] =
                            (acc[u][v] + bias[nc0 + tx * 4 + v]) * scale;
            }
            __syncthreads();
        }
    }
#endif
}

// ===========================================================================
// attention (R6 known-good scalar): one block per (window, head)
// ===========================================================================
__global__ __launch_bounds__(256) void attn_kernel(const float* __restrict__ rpb,
                                                   const int* __restrict__ relidx)
{
    __shared__ float qs[64][33];
    __shared__ float ks[64][33];
    __shared__ float vs[64][33];
    __shared__ float ps[64][68];

    const float* Q  = (const float*)(g_scratch + OFF_Q);
    const float* KV = (const float*)(g_scratch + OFF_KV);
    __nv_bfloat16* AOh = (__nv_bfloat16*)(g_scratch + OFF_AOH);
    __nv_bfloat16* AOl = (__nv_bfloat16*)(g_scratch + OFF_AOL);

    int m = blockIdx.x;
    int h = blockIdx.y;
    int tid = threadIdx.x;
    size_t tb = (size_t)m * 64;

#pragma unroll
    for (int it = 0; it < 8; it++) {
        int idx = tid + it * 256;
        int n = idx >> 5, d = idx & 31;
        qs[n][d] = Q[(tb + n) * 512 + h * 32 + d];
        ks[n][d] = KV[(tb + n) * 1024 + h * 32 + d];
        vs[n][d] = KV[(tb + n) * 1024 + 512 + h * 32 + d];
    }
    __syncthreads();

    {
        int tx = tid & 15, ty = tid >> 4;
        float s[4][4];
#pragma unroll
        for (int u = 0; u < 4; u++)
#pragma unroll
            for (int v = 0; v < 4; v++) s[u][v] = 0.f;
#pragma unroll
        for (int d = 0; d < 32; d++) {
            float a[4], b[4];
#pragma unroll
            for (int u = 0; u < 4; u++) a[u] = qs[ty * 4 + u][d];
#pragma unroll
            for (int v = 0; v < 4; v++) b[v] = ks[tx * 4 + v][d];
#pragma unroll
            for (int u = 0; u < 4; u++)
#pragma unroll
                for (int v = 0; v < 4; v++) s[u][v] += a[u] * b[v];
        }
#pragma unroll
        for (int u = 0; u < 4; u++)
#pragma unroll
            for (int v = 0; v < 4; v++) {
                int mq = ty * 4 + u, nk = tx * 4 + v;
                int ri = relidx[mq * 64 + nk];
                ps[mq][nk] = s[u][v] + rpb[ri * NHEADS + h];
            }
    }
    __syncthreads();

    {
        int g = tid & 3, row = tid >> 2;
        float mx = -1e30f;
        for (int c = g; c < 64; c += 4) mx = fmaxf(mx, ps[row][c]);
        mx = fmaxf(mx, __shfl_xor_sync(0xffffffffu, mx, 1));
        mx = fmaxf(mx, __shfl_xor_sync(0xffffffffu, mx, 2));
        float sum = 0.f;
        for (int c = g; c < 64; c += 4) {
            float e = __expf(ps[row][c] - mx);
            ps[row][c] = e;
            sum += e;
        }
        sum += __shfl_xor_sync(0xffffffffu, sum, 1);
        sum += __shfl_xor_sync(0xffffffffu, sum, 2);
        float inv = 1.f / sum;
        for (int c = g; c < 64; c += 4) ps[row][c] *= inv;
    }
    __syncthreads();

    {
        int tx = tid & 7, ty = tid >> 3;
        float acc[2][4];
#pragma unroll
        for (int u = 0; u < 2; u++)
#pragma unroll
            for (int v = 0; v < 4; v++) acc[u][v] = 0.f;
#pragma unroll
        for (int nk = 0; nk < 64; nk++) {
            float p0 = ps[ty * 2 + 0][nk];
            float p1 = ps[ty * 2 + 1][nk];
#pragma unroll
            for (int v = 0; v < 4; v++) {
                float vv = vs[nk][tx * 4 + v];
                acc[0][v] += p0 * vv;
                acc[1][v] += p1 * vv;
            }
        }
#pragma unroll
        for (int u = 0; u < 2; u++) {
            size_t o = (tb + ty * 2 + u) * 512 + h * 32 + tx * 4;
            unsigned short hh[4], ll[4];
#pragma unroll
            for (int v = 0; v < 4; v++) {
                float x = acc[u][v];
                __nv_bfloat16 hv = __float2bfloat16(x);
                __nv_bfloat16 lv = __float2bfloat16(x - __bfloat162float(hv));
                hh[v] = *(unsigned short*)&hv;
                ll[v] = *(unsigned short*)&lv;
            }
            uint2 ph = make_uint2((uint32_t)hh[0] | ((uint32_t)hh[1] << 16),
                                  (uint32_t)hh[2] | ((uint32_t)hh[3] << 16));
            uint2 pl = make_uint2((uint32_t)ll[0] | ((uint32_t)ll[1] << 16),
                                  (uint32_t)ll[2] | ((uint32_t)ll[3] << 16));
            *(uint2*)(AOh + o) = ph;
            *(uint2*)(AOl + o) = pl;
        }
    }
}

// ===========================================================================
extern "C" void kernel_launch(void* const* d_in, const int* in_sizes, int n_in,
                              void* d_out, int out_size)
{
    const float* xa     = (const float*)d_in[0];
    const float* xb     = (const float*)d_in[1];
    const float* Wq     = (const float*)d_in[2];
    const float* bq     = (const float*)d_in[3];
    const float* Wkv    = (const float*)d_in[4];
    const float* bkv    = (const float*)d_in[5];
    const float* Wo     = (const float*)d_in[6];
    const float* bo     = (const float*)d_in[7];
    const float* rpb    = (const float*)d_in[8];
    const int*   relidx = (const int*)d_in[9];
    float* out = (float*)d_out;

    const float scale = 0.17677669529663687f; // 32^-0.5

    // idempotent, non-enqueuing, capture-safe
    cudaFuncSetAttribute(gemm_bf16x3, cudaFuncAttributeMaxDynamicSharedMemorySize, GEMM_SMEM);

    dim3 gwin(16, 1024);
    // Order: gemmKV is the 4th launch (profiler captures launch #4).
    prep_w_all<<<4096, 256>>>(Wq, Wkv, Wo);                               // 1
    gather_split<<<gwin, 256>>>(xb, OFF_XBH, OFF_XBL);                    // 2
    gather_split<<<gwin, 256>>>(xa, OFF_XAH, OFF_XAL);                    // 3

    gemm_bf16x3<<<dim3(4, 512), GEMM_THREADS, GEMM_SMEM>>>(OFF_XBH, OFF_XBL,  // 4 <- profiled
                                                           OFF_WKVH, OFF_WKVL,
                                                           bkv, OFF_KV, 1024, 1.0f);
    gemm_bf16x3<<<dim3(2, 512), GEMM_THREADS, GEMM_SMEM>>>(OFF_XAH, OFF_XAL,  // 5
                                                           OFF_WQH, OFF_WQL,
                                                           bq, OFF_Q, 512, scale);

    attn_kernel<<<dim3(NWIN, NHEADS), 256>>>(rpb, relidx);                // 6

    gemm_bf16x3<<<dim3(2, 512), GEMM_THREADS, GEMM_SMEM>>>(OFF_AOH, OFF_AOL,  // 7
                                                           OFF_WOH, OFF_WOL,
                                                           bo, OFF_OW, 512, 1.0f);

    scatter_win<<<gwin, 256>>>(out);                                      // 8
}

// round 12
// speedup vs baseline: 1.2665x; 1.1113x over previous
#include <cuda_runtime.h>
#include <cuda_bf16.h>
#include <cstdint>
#include <math.h>

// ===========================================================================
// LocalAttention R12 (= R11 resubmit): tcgen05 bf16x3 GEMMs with
// cp.async.bulk loads from tile-major pre-swizzled (SW64) global layout
// + scalar fp32 attention.
//   A/B GEMM inputs (XA, XB, W, AO) stored as [tile][kb][16KB sw64 block];
//   GEMM producer = 1 elected thread issuing 4x16KB bulk copies per kb.
// ===========================================================================

#if defined(__CUDA_ARCH_FEAT_SM103_ALL) || defined(__CUDA_ARCH_FEAT_SM100_ALL) || defined(__CUDA_ARCH_FEAT_SM101_ALL)
#define HAS_TCGEN05 1
#else
#define HAS_TCGEN05 0
#endif

#define TOK      131072
#define NWIN     2048
#define NHEADS   16

// ---- scratch regions (byte offsets) ----
#define OFF_XAH  0ull
#define OFF_XAL  134217728ull
#define OFF_XBH  268435456ull
#define OFF_XBL  402653184ull
#define OFF_Q    536870912ull      // fp32 [TOK,512] row-major
#define OFF_KV   805306368ull      // fp32 [TOK,1024] row-major
#define OFF_AOH  OFF_XAH           // aliases XA (dead after Q GEMM)
#define OFF_AOL  OFF_XAL
#define OFF_OW   OFF_XBH           // fp32 [TOK,512] row-major, aliases XB
#define OFF_WQH  1342177280ull
#define OFF_WQL  1342701568ull
#define OFF_WKVH 1343225856ull
#define OFF_WKVL 1344274432ull
#define OFF_WOH  1345323008ull
#define OFF_WOL  1345847296ull

__device__ __align__(1024) unsigned char g_scratch[1346371584ull];

// ===========================================================================
// PTX helpers
// ===========================================================================
__device__ __forceinline__ uint32_t smem_u32(const void* p) {
    uint32_t a;
    asm("{ .reg .u64 t; cvta.to.shared.u64 t, %1; cvt.u32.u64 %0, t; }" : "=r"(a) : "l"(p));
    return a;
}
__device__ __forceinline__ uint32_t elect_one() {
    uint32_t pred;
    asm volatile("{\n\t.reg .pred p;\n\telect.sync _|p, 0xFFFFFFFF;\n\tselp.b32 %0, 1, 0, p;\n\t}" : "=r"(pred));
    return pred;
}
#define MBARRIER_INIT(addr, cnt) \
    asm volatile("mbarrier.init.shared.b64 [%0], %1;" :: "r"((uint32_t)(addr)), "r"((uint32_t)(cnt)) : "memory")
#define MBARRIER_INVAL(addr) \
    asm volatile("mbarrier.inval.shared.b64 [%0];" :: "r"((uint32_t)(addr)) : "memory")
#define MBARRIER_EXPECT_TX(addr, bytes) \
    asm volatile("mbarrier.arrive.expect_tx.shared.b64 _, [%0], %1;" \
        :: "r"((uint32_t)(addr)), "r"((uint32_t)(bytes)) : "memory")
#define MBARRIER_WAIT_PARITY(addr, par) do { \
    uint32_t _mb = (uint32_t)(addr); uint32_t _p = (uint32_t)(par); uint32_t _done; \
    asm volatile("{\n\t.reg .pred p;\n\t" \
        "mbarrier.try_wait.parity.acquire.cta.shared::cta.b64 p, [%1], %2;\n\t" \
        "selp.b32 %0, 1, 0, p;\n\t}" : "=r"(_done) : "r"(_mb), "r"(_p) : "memory"); \
    if (!_done) { \
        asm volatile("{\n\t.reg .pred P1;\n\t" \
            "WAIT_LOOP_%=:\n\t" \
            "mbarrier.try_wait.parity.acquire.cta.shared::cta.b64 P1, [%0], %1, 0x989680;\n\t" \
            "@P1 bra.uni WAIT_DONE_%=;\n\t" \
            "bra.uni WAIT_LOOP_%=;\n\t" \
            "WAIT_DONE_%=:\n\t}" :: "r"(_mb), "r"(_p) : "memory"); \
    } } while (0)

// bulk async copy global->shared with mbarrier transaction completion (sm_90)
__device__ __forceinline__ void bulk_g2s(uint32_t dst, const void* src,
                                         uint32_t bytes, uint32_t mbar) {
    asm volatile(
        "cp.async.bulk.shared::cluster.global.mbarrier::complete_tx::bytes [%0], [%1], %2, [%3];"
        :: "r"(dst), "l"(src), "r"(bytes), "r"(mbar) : "memory");
}

#if HAS_TCGEN05
#define TCGEN05_ALLOC(sm, n) \
    asm volatile("tcgen05.alloc.cta_group::1.sync.aligned.shared::cta.b32 [%0], %1;" \
        :: "r"((uint32_t)(sm)), "r"((uint32_t)(n)) : "memory")
#define TCGEN05_DEALLOC(t, n) \
    asm volatile("tcgen05.dealloc.cta_group::1.sync.aligned.b32 %0, %1;" :: "r"(t), "r"((uint32_t)(n)))
#define TCGEN05_RELINQ() \
    asm volatile("tcgen05.relinquish_alloc_permit.cta_group::1.sync.aligned;")
#define TCGEN05_COMMIT(mb) \
    asm volatile("tcgen05.commit.cta_group::1.mbarrier::arrive::one.shared::cluster.b64 [%0];" \
        :: "r"((uint32_t)(mb)) : "memory")
#define TCGEN05_FENCE_AFTER()  asm volatile("tcgen05.fence::after_thread_sync;" ::: "memory")
#define TCGEN05_FENCE_BEFORE() asm volatile("tcgen05.fence::before_thread_sync;" ::: "memory")
#define TCGEN05_WAIT_LD()      asm volatile("tcgen05.wait::ld.sync.aligned;" ::: "memory")

#define TCGEN05_LD_X32(r, ta) \
    asm volatile("tcgen05.ld.sync.aligned.32x32b.x32.b32 " \
        "{%0, %1, %2, %3, %4, %5, %6, %7, " \
        " %8, %9, %10, %11, %12, %13, %14, %15, " \
        " %16, %17, %18, %19, %20, %21, %22, %23, " \
        " %24, %25, %26, %27, %28, %29, %30, %31}, [%32];" \
        : "=r"((r)[0]),  "=r"((r)[1]),  "=r"((r)[2]),  "=r"((r)[3]), \
          "=r"((r)[4]),  "=r"((r)[5]),  "=r"((r)[6]),  "=r"((r)[7]), \
          "=r"((r)[8]),  "=r"((r)[9]),  "=r"((r)[10]), "=r"((r)[11]), \
          "=r"((r)[12]), "=r"((r)[13]), "=r"((r)[14]), "=r"((r)[15]), \
          "=r"((r)[16]), "=r"((r)[17]), "=r"((r)[18]), "=r"((r)[19]), \
          "=r"((r)[20]), "=r"((r)[21]), "=r"((r)[22]), "=r"((r)[23]), \
          "=r"((r)[24]), "=r"((r)[25]), "=r"((r)[26]), "=r"((r)[27]), \
          "=r"((r)[28]), "=r"((r)[29]), "=r"((r)[30]), "=r"((r)[31]) \
        : "r"(ta))

__device__ __forceinline__ void mma_bf16_ss(uint32_t d, uint64_t ad, uint64_t bd,
                                            uint32_t idesc, uint32_t en) {
    asm volatile("{\n\t.reg .pred p;\n\tsetp.ne.u32 p, %5, 0;\n\t"
        "tcgen05.mma.cta_group::1.kind::f16 [%0], %1, %2, %3, {%4, %4, %4, %4}, p;\n\t}"
        :: "r"(d), "l"(ad), "l"(bd), "r"(idesc), "r"(0u), "r"(en) : "memory");
}
#endif // HAS_TCGEN05

// SW64 smem descriptor: layout=4, version=1, SBO=32, LBO=1
static constexpr uint64_t SMEM_DESC_BASE_SW64 =
    (uint64_t(4) << 61) | (uint64_t(1) << 46) | (uint64_t(32) << 32) | (uint64_t(1) << 16);
#define MAKE_SMEM_DESC64(a) (SMEM_DESC_BASE_SW64 | ((uint64_t)((a) >> 4) & 0x3FFF))

__device__ __forceinline__ uint32_t sw64(uint32_t o) { return o ^ ((o >> 3) & 0x30); }

// tile-major addressing: operand stored as [tile][kb 0..15][16KB sw64 block];
// element (row 0..255 within tile, k 0..511) lives at:
__device__ __forceinline__ size_t tm_addr(int tile, int row, int k) {
    return (size_t)(tile * 16 + (k >> 5)) * 16384u + sw64((uint32_t)(row * 64 + (k & 31) * 2));
}

// kind::f16 SS MMA idesc: D=fp32, A=B=bf16, M=128, N=128
static constexpr uint32_t GEMM_IDESC =
    (1u << 4) | (1u << 7) | (1u << 10) | ((128u / 8) << 17) | ((128u / 16) << 24);

// ===========================================================================
// prep_w_all: weights fp32 -> bf16 hi/lo, tile-major sw64 layout
// ===========================================================================
__global__ __launch_bounds__(256) void prep_w_all(const float* __restrict__ Wq,
                                                  const float* __restrict__ Wkv,
                                                  const float* __restrict__ Wo)
{
    int i = blockIdx.x * 256 + threadIdx.x;
    const float* src; size_t hiOff, loOff; int j;
    if (i < 262144)      { src = Wq;  hiOff = OFF_WQH;  loOff = OFF_WQL;  j = i; }
    else if (i < 786432) { src = Wkv; hiOff = OFF_WKVH; loOff = OFF_WKVL; j = i - 262144; }
    else                 { src = Wo;  hiOff = OFF_WOH;  loOff = OFF_WOL;  j = i - 786432; }
    float x = src[j];
    __nv_bfloat16 h = __float2bfloat16(x);
    __nv_bfloat16 l = __float2bfloat16(x - __bfloat162float(h));
    int n = j >> 9, c = j & 511;               // row n, col c (K=512)
    size_t a = tm_addr(n >> 8, n & 255, c);
    *(__nv_bfloat16*)(g_scratch + hiOff + a) = h;
    *(__nv_bfloat16*)(g_scratch + loOff + a) = l;
}

// ===========================================================================
// gather_split: [B,C,H,W] fp32 -> tile-major sw64 bf16 hi/lo (token rows)
// ===========================================================================
__global__ __launch_bounds__(256) void gather_split(const float* __restrict__ src,
                                                    size_t hiOff, size_t loOff)
{
    __shared__ float tile[32][129];
    int bh = blockIdx.y;
    int b = bh >> 7, h = bh & 127;
    int c0 = blockIdx.x << 5;
    int tid = threadIdx.x;

    const float* srow = src + ((size_t)(b * 512 + c0) * 128 + h) * 128;
#pragma unroll
    for (int it = 0; it < 16; it++) {
        int idx = tid + it * 256;
        int cc = idx >> 7, w = idx & 127;
        tile[cc][w] = srow[(size_t)cc * 16384 + w];
    }
    __syncthreads();
    int r1 = h >> 3, i = h & 7;
#pragma unroll
    for (int it = 0; it < 16; it++) {
        int idx = tid + it * 256;
        int w = idx >> 5, cc = idx & 31;
        int r2 = w >> 3, j = w & 7;
        int t = ((b * 256 + r1 * 16 + r2) << 6) + i * 8 + j;
        float x = tile[cc][w];
        __nv_bfloat16 hv = __float2bfloat16(x);
        __nv_bfloat16 lv = __float2bfloat16(x - __bfloat162float(hv));
        size_t a = tm_addr(t >> 8, t & 255, c0 + cc);
        *(__nv_bfloat16*)(g_scratch + hiOff + a) = hv;
        *(__nv_bfloat16*)(g_scratch + loOff + a) = lv;
    }
}

// ===========================================================================
// scatter: row-major fp32 OW [TOK,512] -> [B,C,H,W]
// ===========================================================================
__global__ __launch_bounds__(256) void scatter_win(float* __restrict__ dst)
{
    __shared__ float tile[32][129];
    const float* srcw = (const float*)(g_scratch + OFF_OW);
    int bh = blockIdx.y;
    int b = bh >> 7, h = bh & 127;
    int c0 = blockIdx.x << 5;
    int tid = threadIdx.x;
    int r1 = h >> 3, i = h & 7;

#pragma unroll
    for (int it = 0; it < 16; it++) {
        int idx = tid + it * 256;
        int w = idx >> 5, cc = idx & 31;
        int r2 = w >> 3, j = w & 7;
        int t = ((b * 256 + r1 * 16 + r2) << 6) + i * 8 + j;
        tile[cc][w] = srcw[(size_t)t * 512 + c0 + cc];
    }
    __syncthreads();
    float* drow = dst + ((size_t)(b * 512 + c0) * 128 + h) * 128;
#pragma unroll
    for (int it = 0; it < 16; it++) {
        int idx = tid + it * 256;
        int cc = idx >> 7, w = idx & 127;
        drow[(size_t)cc * 16384 + w] = tile[cc][w];
    }
}

// ===========================================================================
// gemm_bf16x3: 256x256xBK32 tiles, depth-3, cp.async.bulk producer (warp 0
// elected lane) + MMA issuer (warp 8). Inputs tile-major sw64; C row-major.
// smem: [0] tmem ptr | full[3]@16,24,32 (cnt 1 + tx) | free[3]@40,48,56 (cnt 1)
//       | done@64 (cnt 1) | buffers @1024 + s*65536 (Ah|Al|Bh|Bl 16KB each)
// ===========================================================================
#define GEMM_SMEM  197632
#define GEMM_THREADS 288

__global__ __launch_bounds__(GEMM_THREADS) void gemm_bf16x3(
    size_t ahOff, size_t alOff, size_t bhOff, size_t blOff,
    const float* __restrict__ bias, size_t cOff, int No, float scale)
{
    extern __shared__ char smem[];
    const unsigned char* AhB = g_scratch + ahOff;
    const unsigned char* AlB = g_scratch + alOff;
    const unsigned char* BhB = g_scratch + bhOff;
    const unsigned char* BlB = g_scratch + blOff;
    float* C = (float*)(g_scratch + cOff);

    int tid = threadIdx.x, wid = tid >> 5, lid = tid & 31;
    int bx = blockIdx.x, by = blockIdx.y;
    int n0 = bx * 256, m0 = by * 256;

#if HAS_TCGEN05
    uint32_t sbase = smem_u32(smem);

    if (wid == 0) TCGEN05_ALLOC(sbase, 512);
    __syncthreads();
    uint32_t tmem;
    asm volatile("ld.shared.b32 %0, [%1];" : "=r"(tmem) : "r"(sbase));
    if (tid == 0) {
#pragma unroll
        for (int s = 0; s < 3; s++) {
            MBARRIER_INIT(sbase + 16 + 8 * s, 1);    // full[s] (arrive 1 + tx)
            MBARRIER_INIT(sbase + 40 + 8 * s, 1);    // free[s]
        }
        MBARRIER_INIT(sbase + 64, 1);                // done
    }
    __syncthreads();

    if (wid == 0) {
        // -------- producer: warp 0 (waits full-warp, elected lane issues) --------
        for (int kb = 0; kb < 16; kb++) {
            int buf = kb % 3;
            uint32_t bo = 1024u + (uint32_t)buf * 65536u;
            if (kb >= 3) {
                int t = kb / 3;
                MBARRIER_WAIT_PARITY(sbase + 40 + 8 * buf, (t - 1) & 1);
            }
            if (elect_one()) {
                MBARRIER_EXPECT_TX(sbase + 16 + 8 * buf, 65536u);
                size_t ba = (size_t)(by * 16 + kb) * 16384u;
                size_t bb = (size_t)(bx * 16 + kb) * 16384u;
                uint32_t mb = sbase + 16 + 8 * buf;
                bulk_g2s(sbase + bo,          AhB + ba, 16384u, mb);
                bulk_g2s(sbase + bo + 16384,  AlB + ba, 16384u, mb);
                bulk_g2s(sbase + bo + 32768,  BhB + bb, 16384u, mb);
                bulk_g2s(sbase + bo + 49152,  BlB + bb, 16384u, mb);
            }
        }
    } else if (wid == 8) {
        // -------- MMA issuer: warp 8 --------
        for (int kb = 0; kb < 16; kb++) {
            int buf = kb % 3;
            uint32_t bo = 1024u + (uint32_t)buf * 65536u;
            int t = kb / 3;
            MBARRIER_WAIT_PARITY(sbase + 16 + 8 * buf, t & 1);
            if (elect_one()) {
                uint64_t dA[2] = { MAKE_SMEM_DESC64(sbase + bo),
                                   MAKE_SMEM_DESC64(sbase + bo + 16384) };
                uint64_t dB[2] = { MAKE_SMEM_DESC64(sbase + bo + 32768),
                                   MAKE_SMEM_DESC64(sbase + bo + 49152) };
                const int pa[3] = {0, 1, 0}, pb[3] = {0, 0, 1};
#pragma unroll
                for (int p = 0; p < 3; p++) {
                    uint64_t ad = dA[pa[p]], bd = dB[pb[p]];
#pragma unroll
                    for (int ks = 0; ks < 2; ks++) {
                        uint32_t en = !(kb == 0 && p == 0 && ks == 0);
#pragma unroll
                        for (int mh = 0; mh < 2; mh++) {
                            uint64_t adm = ad + mh * 512 + ks * 2;
                            mma_bf16_ss(tmem + mh * 256,       adm, bd + ks * 2,       GEMM_IDESC, en);
                            mma_bf16_ss(tmem + mh * 256 + 128, adm, bd + 512 + ks * 2, GEMM_IDESC, en);
                        }
                    }
                }
                // last kb commits to the dedicated done barrier; others to free[buf]
                TCGEN05_COMMIT((kb == 15) ? (sbase + 64) : (sbase + 40 + 8 * buf));
            }
        }
    }

    // everyone waits for the final MMA group (done completion #1 -> parity 0)
    MBARRIER_WAIT_PARITY(sbase + 64, 0);
    TCGEN05_FENCE_AFTER();

    // ---- epilogue: direct TMEM -> registers -> STG.128 (warps 0-7) ----
    if (wid < 8) {
        int sp = wid & 3;             // subpartition rows sp*32 + lid
        int cbase = (wid >> 2) * 128; // warps 0-3: cols 0-127, 4-7: 128-255
#pragma unroll 1
        for (int mh = 0; mh < 2; mh++) {
            int row = m0 + mh * 128 + sp * 32 + lid;
            float* Crow = C + (size_t)row * No + n0 + cbase;
#pragma unroll
            for (int cc = 0; cc < 128; cc += 32) {
                uint32_t r[32];
                TCGEN05_LD_X32(r, tmem + mh * 256 + cbase + cc);
                TCGEN05_WAIT_LD();
#pragma unroll
                for (int i = 0; i < 8; i++) {
                    float4 b = *(const float4*)(bias + n0 + cbase + cc + 4 * i);
                    float4 o;
                    o.x = (__uint_as_float(r[4 * i + 0]) + b.x) * scale;
                    o.y = (__uint_as_float(r[4 * i + 1]) + b.y) * scale;
                    o.z = (__uint_as_float(r[4 * i + 2]) + b.z) * scale;
                    o.w = (__uint_as_float(r[4 * i + 3]) + b.w) * scale;
                    *(float4*)(Crow + cc + 4 * i) = o;
                }
            }
        }
        TCGEN05_FENCE_BEFORE();
    }

    __syncthreads();
    if (tid == 0) {
#pragma unroll
        for (int s = 0; s < 3; s++) {
            MBARRIER_INVAL(sbase + 16 + 8 * s);
            MBARRIER_INVAL(sbase + 40 + 8 * s);
        }
        MBARRIER_INVAL(sbase + 64);
    }
    __syncthreads();
    if (wid == 0) { TCGEN05_RELINQ(); TCGEN05_DEALLOC(tmem, 512); }

#else  // ---- FFMA fallback for the plain compute_103 pass (tile-major reads) ----
    float* As = (float*)smem;
    float* Bs = (float*)(smem + 16 * 128 * 4);
    int tx = tid & 15, ty = tid >> 4;

    for (int msub = 0; msub < 2; msub++) {
        for (int nsub = 0; nsub < 4; nsub++) {
            int nc0 = n0 + nsub * 64;
            float acc[8][4];
#pragma unroll
            for (int u = 0; u < 8; u++)
#pragma unroll
                for (int v = 0; v < 4; v++) acc[u][v] = 0.f;

            for (int k0 = 0; k0 < 512; k0 += 16) {
                if (tid < 256) {
#pragma unroll
                    for (int t = 0; t < 8; t++) {
                        int e = tid + t * 256;
                        int r = e & 127, kk = e >> 7;
                        size_t a = tm_addr(by, msub * 128 + r, k0 + kk);
                        As[kk * 128 + r] = __bfloat162float(*(const __nv_bfloat16*)(AhB + a))
                                         + __bfloat162float(*(const __nv_bfloat16*)(AlB + a));
                    }
#pragma unroll
                    for (int t = 0; t < 4; t++) {
                        int e = tid + t * 256;
                        int r = e & 63, kk = e >> 6;
                        size_t a = tm_addr(bx, nsub * 64 + r, k0 + kk);
                        Bs[kk * 64 + r] = __bfloat162float(*(const __nv_bfloat16*)(BhB + a))
                                        + __bfloat162float(*(const __nv_bfloat16*)(BlB + a));
                    }
                }
                __syncthreads();
                if (tid < 256) {
#pragma unroll
                    for (int kk = 0; kk < 16; kk++) {
                        float a[8], b[4];
#pragma unroll
                        for (int u = 0; u < 8; u++) a[u] = As[kk * 128 + ty * 8 + u];
#pragma unroll
                        for (int v = 0; v < 4; v++) b[v] = Bs[kk * 64 + tx * 4 + v];
#pragma unroll
                        for (int u = 0; u < 8; u++)
#pragma unroll
                            for (int v = 0; v < 4; v++) acc[u][v] += a[u] * b[v];
                    }
                }
                __syncthreads();
            }

            if (tid < 256) {
#pragma unroll
                for (int u = 0; u < 8; u++)
#pragma unroll
                    for (int v = 0; v < 4; v++)
                        C[(size_t)(m0 + msub * 128 + ty * 8 + u) * No + nc0 + tx * 4 + v] =
                            (acc[u][v] + bias[nc0 + tx * 4 + v]) * scale;
            }
            __syncthreads();
        }
    }
#endif
}

// ===========================================================================
// attention: scalar fp32 (R6 known-good math); AO written tile-major sw64.
// ===========================================================================
__global__ __launch_bounds__(256) void attn_kernel(const float* __restrict__ rpb,
                                                   const int* __restrict__ relidx)
{
    __shared__ float qs[64][33];
    __shared__ float ks[64][33];
    __shared__ float vs[64][33];
    __shared__ float ps[64][68];

    const float* Q  = (const float*)(g_scratch + OFF_Q);
    const float* KV = (const float*)(g_scratch + OFF_KV);

    int m = blockIdx.x;
    int h = blockIdx.y;
    int tid = threadIdx.x;
    size_t tb = (size_t)m * 64;

#pragma unroll
    for (int it = 0; it < 8; it++) {
        int idx = tid + it * 256;
        int n = idx >> 5, d = idx & 31;
        qs[n][d] = Q[(tb + n) * 512 + h * 32 + d];
        ks[n][d] = KV[(tb + n) * 1024 + h * 32 + d];
        vs[n][d] = KV[(tb + n) * 1024 + 512 + h * 32 + d];
    }
    __syncthreads();

    {
        int tx = tid & 15, ty = tid >> 4;
        float s[4][4];
#pragma unroll
        for (int u = 0; u < 4; u++)
#pragma unroll
            for (int v = 0; v < 4; v++) s[u][v] = 0.f;
#pragma unroll
        for (int d = 0; d < 32; d++) {
            float a[4], b[4];
#pragma unroll
            for (int u = 0; u < 4; u++) a[u] = qs[ty * 4 + u][d];
#pragma unroll
            for (int v = 0; v < 4; v++) b[v] = ks[tx * 4 + v][d];
#pragma unroll
            for (int u = 0; u < 4; u++)
#pragma unroll
                for (int v = 0; v < 4; v++) s[u][v] += a[u] * b[v];
        }
#pragma unroll
        for (int u = 0; u < 4; u++)
#pragma unroll
            for (int v = 0; v < 4; v++) {
                int mq = ty * 4 + u, nk = tx * 4 + v;
                int ri = relidx[mq * 64 + nk];
                ps[mq][nk] = s[u][v] + rpb[ri * NHEADS + h];
            }
    }
    __syncthreads();

    {
        int g = tid & 3, row = tid >> 2;
        float mx = -1e30f;
        for (int c = g; c < 64; c += 4) mx = fmaxf(mx, ps[row][c]);
        mx = fmaxf(mx, __shfl_xor_sync(0xffffffffu, mx, 1));
        mx = fmaxf(mx, __shfl_xor_sync(0xffffffffu, mx, 2));
        float sum = 0.f;
        for (int c = g; c < 64; c += 4) {
            float e = __expf(ps[row][c] - mx);
            ps[row][c] = e;
            sum += e;
        }
        sum += __shfl_xor_sync(0xffffffffu, sum, 1);
        sum += __shfl_xor_sync(0xffffffffu, sum, 2);
        float inv = 1.f / sum;
        for (int c = g; c < 64; c += 4) ps[row][c] *= inv;
    }
    __syncthreads();

    {
        int tx = tid & 7, ty = tid >> 3;
        float acc[2][4];
#pragma unroll
        for (int u = 0; u < 2; u++)
#pragma unroll
            for (int v = 0; v < 4; v++) acc[u][v] = 0.f;
#pragma unroll
        for (int nk = 0; nk < 64; nk++) {
            float p0 = ps[ty * 2 + 0][nk];
            float p1 = ps[ty * 2 + 1][nk];
#pragma unroll
            for (int v = 0; v < 4; v++) {
                float vv = vs[nk][tx * 4 + v];
                acc[0][v] += p0 * vv;
                acc[1][v] += p1 * vv;
            }
        }
        // AO written tile-major sw64 (kb = h since col = h*32 + tx*4)
#pragma unroll
        for (int u = 0; u < 2; u++) {
            int t = (int)tb + ty * 2 + u;
            unsigned short hh[4], ll[4];
#pragma unroll
            for (int v = 0; v < 4; v++) {
                float x = acc[u][v];
                __nv_bfloat16 hv = __float2bfloat16(x);
                __nv_bfloat16 lv = __float2bfloat16(x - __bfloat162float(hv));
                hh[v] = *(unsigned short*)&hv;
                ll[v] = *(unsigned short*)&lv;
            }
            uint2 ph = make_uint2((uint32_t)hh[0] | ((uint32_t)hh[1] << 16),
                                  (uint32_t)hh[2] | ((uint32_t)hh[3] << 16));
            uint2 pl = make_uint2((uint32_t)ll[0] | ((uint32_t)ll[1] << 16),
                                  (uint32_t)ll[2] | ((uint32_t)ll[3] << 16));
            size_t a = tm_addr(t >> 8, t & 255, h * 32 + tx * 4);  // 8B-aligned
            *(uint2*)(g_scratch + OFF_AOH + a) = ph;
            *(uint2*)(g_scratch + OFF_AOL + a) = pl;
        }
    }
}

// ===========================================================================
extern "C" void kernel_launch(void* const* d_in, const int* in_sizes, int n_in,
                              void* d_out, int out_size)
{
    const float* xa     = (const float*)d_in[0];
    const float* xb     = (const float*)d_in[1];
    const float* Wq     = (const float*)d_in[2];
    const float* bq     = (const float*)d_in[3];
    const float* Wkv    = (const float*)d_in[4];
    const float* bkv    = (const float*)d_in[5];
    const float* Wo     = (const float*)d_in[6];
    const float* bo     = (const float*)d_in[7];
    const float* rpb    = (const float*)d_in[8];
    const int*   relidx = (const int*)d_in[9];
    float* out = (float*)d_out;

    const float scale = 0.17677669529663687f; // 32^-0.5

    // idempotent, non-enqueuing, capture-safe
    cudaFuncSetAttribute(gemm_bf16x3, cudaFuncAttributeMaxDynamicSharedMemorySize, GEMM_SMEM);

    dim3 gwin(16, 1024);
    // Order: gemmKV is the 4th launch (profiler captures launch #4).
    prep_w_all<<<4096, 256>>>(Wq, Wkv, Wo);                               // 1
    gather_split<<<gwin, 256>>>(xb, OFF_XBH, OFF_XBL);                    // 2
    gather_split<<<gwin, 256>>>(xa, OFF_XAH, OFF_XAL);                    // 3

    gemm_bf16x3<<<dim3(4, 512), GEMM_THREADS, GEMM_SMEM>>>(OFF_XBH, OFF_XBL,  // 4 <- profiled
                                                           OFF_WKVH, OFF_WKVL,
                                                           bkv, OFF_KV, 1024, 1.0f);
    gemm_bf16x3<<<dim3(2, 512), GEMM_THREADS, GEMM_SMEM>>>(OFF_XAH, OFF_XAL,  // 5
                                                           OFF_WQH, OFF_WQL,
                                                           bq, OFF_Q, 512, scale);

    attn_kernel<<<dim3(NWIN, NHEADS), 256>>>(rpb, relidx);                // 6

    gemm_bf16x3<<<dim3(2, 512), GEMM_THREADS, GEMM_SMEM>>>(OFF_AOH, OFF_AOL,  // 7
                                                           OFF_WOH, OFF_WOL,
                                                           bo, OFF_OW, 512, 1.0f);

    scatter_win<<<gwin, 256>>>(out);                                      // 8
}